// round 14
// baseline (speedup 1.0000x reference)
#include <cuda_runtime.h>
#include <cuda_bf16.h>
#include <cstdint>

#define D      512
#define NWAY   64
#define KSHOT  16
#define MAXQ   8192
#define SA     72            // smem K-stride (bf16): 144B rows, LDSM conflict-free
#define PA     (64 * SA)
#define PB     (128 * SA)
#define ASZ2   (256 * SA)    // main A stage elems (256 rows)
#define BSZ2   (128 * SA)    // main B stage elems (128 rows)

// ---------------- device scratch ----------------
__device__ __nv_bfloat16  g_smeanbf[NWAY * D];
__device__ __nv_bfloat16  g_Pbf[NWAY * D];
__device__ float          g_Ppart[8 * NWAY * D];
__device__ float          g_Rpart[8 * NWAY * D];
__device__ float          g_pcterm[NWAY];
__device__ __nv_bfloat16  g_qbf[(size_t)MAXQ * D];
__device__ __nv_bfloat16  g_Bbig[(512 + 128) * D];   // 0..511 W, 512..575 R, 576..639 zero pad
__device__ __nv_bfloat16  g_WbfT[D * D];
__device__ float          g_partial[(size_t)MAXQ * 8];
__device__ float          g_cross[(size_t)MAXQ * NWAY];

// ---------------- mma / ldmatrix / cp.async helpers ----------------
__device__ __forceinline__ void mma16816(float* c,
                                         uint32_t a0, uint32_t a1, uint32_t a2, uint32_t a3,
                                         uint32_t b0, uint32_t b1) {
    asm volatile(
        "mma.sync.aligned.m16n8k16.row.col.f32.bf16.bf16.f32 "
        "{%0,%1,%2,%3},{%4,%5,%6,%7},{%8,%9},{%0,%1,%2,%3};\n"
        : "+f"(c[0]), "+f"(c[1]), "+f"(c[2]), "+f"(c[3])
        : "r"(a0), "r"(a1), "r"(a2), "r"(a3), "r"(b0), "r"(b1));
}
__device__ __forceinline__ void ldsm4(uint32_t* r, uint32_t a) {
    asm volatile("ldmatrix.sync.aligned.m8n8.x4.shared.b16 {%0,%1,%2,%3}, [%4];"
                 : "=r"(r[0]), "=r"(r[1]), "=r"(r[2]), "=r"(r[3]) : "r"(a));
}
__device__ __forceinline__ void cp_async16(void* smem, const void* gmem) {
    uint32_t s = (uint32_t)__cvta_generic_to_shared(smem);
    asm volatile("cp.async.cg.shared.global [%0], [%1], 16;\n" :: "r"(s), "l"(gmem));
}
#define CP_COMMIT() asm volatile("cp.async.commit_group;\n")
#define CP_WAIT(n)  asm volatile("cp.async.wait_group %0;\n" :: "n"(n))

// Small-tile step (64Mx128N CTA, warp 32x32): prologue GEMMs
__device__ __forceinline__ void tile_step_small(float acc[2][4][4], uint32_t aA, uint32_t aB,
                                                int aOff0, int aOff1, int bOff0, int bOff1) {
    #pragma unroll
    for (int kk = 0; kk < 64; kk += 16) {
        uint32_t br0[4], br1[4];
        ldsm4(br0, aB + bOff0 + kk * 2);
        ldsm4(br1, aB + bOff1 + kk * 2);
        #pragma unroll
        for (int mf = 0; mf < 2; mf++) {
            uint32_t ar[4];
            ldsm4(ar, aA + (mf ? aOff1 : aOff0) + kk * 2);
            mma16816(acc[mf][0], ar[0], ar[1], ar[2], ar[3], br0[0], br0[1]);
            mma16816(acc[mf][1], ar[0], ar[1], ar[2], ar[3], br0[2], br0[3]);
            mma16816(acc[mf][2], ar[0], ar[1], ar[2], ar[3], br1[0], br1[1]);
            mma16816(acc[mf][3], ar[0], ar[1], ar[2], ar[3], br1[2], br1[3]);
        }
    }
}

// ---------------- prep_q: Q -> bf16 ----------------
__global__ void prep_q_kernel(const float* __restrict__ q, int M) {
    size_t total = (size_t)M * D;
    size_t base = (size_t)blockIdx.x * 2048 + threadIdx.x * 8;
    if (base + 8 <= total) {
        float4 v0 = *(const float4*)(q + base);
        float4 v1 = *(const float4*)(q + base + 4);
        __nv_bfloat162 p0 = __floats2bfloat162_rn(v0.x, v0.y);
        __nv_bfloat162 p1 = __floats2bfloat162_rn(v0.z, v0.w);
        __nv_bfloat162 p2 = __floats2bfloat162_rn(v1.x, v1.y);
        __nv_bfloat162 p3 = __floats2bfloat162_rn(v1.z, v1.w);
        uint4 o;
        o.x = *(uint32_t*)&p0; o.y = *(uint32_t*)&p1;
        o.z = *(uint32_t*)&p2; o.w = *(uint32_t*)&p3;
        *(uint4*)(g_qbf + base) = o;
    } else {
        for (int e = 0; e < 8; e++)
            if (base + e < total) g_qbf[base + e] = __float2bfloat16(q[base + e]);
    }
}

// ---------------- prep_w: W->bf16, W^T, smean, zero pad ----------------
__global__ void prep_w_kernel(const float* __restrict__ W,
                              const float* __restrict__ support) {
    int b = blockIdx.x;
    int tid = threadIdx.x;
    if (b < 256) {
        int base = b * 1024 + tid * 4;
        float4 v = *(const float4*)(W + base);
        *(__nv_bfloat162*)(g_Bbig + base)     = __floats2bfloat162_rn(v.x, v.y);
        *(__nv_bfloat162*)(g_Bbig + base + 2) = __floats2bfloat162_rn(v.z, v.w);
    } else if (b < 256 + 64) {
        __shared__ float ts[64][68];
        int t = b - 256;
        int r0 = (t >> 3) * 64, c0 = (t & 7) * 64;
        #pragma unroll
        for (int it = 0; it < 4; it++) {
            int r = (tid >> 4) + it * 16;
            float4 v = *(const float4*)(W + (size_t)(r0 + r) * D + c0 + (tid & 15) * 4);
            ts[r][(tid & 15) * 4 + 0] = v.x; ts[r][(tid & 15) * 4 + 1] = v.y;
            ts[r][(tid & 15) * 4 + 2] = v.z; ts[r][(tid & 15) * 4 + 3] = v.w;
        }
        __syncthreads();
        int kk = tid >> 2, jb = (tid & 3) * 16;
        #pragma unroll
        for (int e = 0; e < 16; e += 2) {
            *(__nv_bfloat162*)(g_WbfT + (size_t)(c0 + kk) * D + r0 + jb + e) =
                __floats2bfloat162_rn(ts[jb + e][kk], ts[jb + e + 1][kk]);
        }
    } else if (b < 256 + 64 + 64) {
        int c = b - 256 - 64;
        for (int col = tid; col < D; col += blockDim.x) {
            float s = 0.f;
            #pragma unroll
            for (int k = 0; k < KSHOT; k++) s += support[(size_t)(c * KSHOT + k) * D + col];
            g_smeanbf[c * D + col] = __float2bfloat16(s * (1.f / KSHOT));
        }
    } else {
        // zero pad rows 576..639 of Bbig
        int t = b - 256 - 64 - 64;
        uint4 z = make_uint4(0u, 0u, 0u, 0u);
        *(uint4*)(g_Bbig + (size_t)576 * D + (size_t)t * 2048 + tid * 8) = z;
    }
}

// ---------------- proj: Ppart[ks] = smeanbf @ W^T (grid (4 j-tiles, 8 ks)) ----------------
__global__ __launch_bounds__(256) void proj_gemm(int dummy) {
    __shared__ __nv_bfloat16 sA[PA];
    __shared__ __nv_bfloat16 sB[PB];
    int tid = threadIdx.x;
    int n0 = blockIdx.x * 128;
    int ks = blockIdx.y;
    int warp = tid >> 5, lane = tid & 31;
    int wm = warp & 1, wn = warp >> 1;
    int g = lane >> 2, t4 = lane & 3;

    int aOff0 = (((wm * 32 + 0 + (lane & 15)) * SA + (lane >> 4) * 8)) * 2;
    int aOff1 = (((wm * 32 + 16 + (lane & 15)) * SA + (lane >> 4) * 8)) * 2;
    int bOff0 = (((wn * 32 + 0 + (lane & 7) + ((lane >> 4) << 3)) * SA + ((lane >> 3) & 1) * 8)) * 2;
    int bOff1 = (((wn * 32 + 16 + (lane & 7) + ((lane >> 4) << 3)) * SA + ((lane >> 3) & 1) * 8)) * 2;

    #pragma unroll
    for (int j = 0; j < 2; j++) {
        int i = tid + j * 256, r = i >> 3, c8 = i & 7;
        cp_async16(sA + r * SA + c8 * 8, g_smeanbf + (size_t)r * D + ks * 64 + c8 * 8);
    }
    #pragma unroll
    for (int j = 0; j < 4; j++) {
        int i = tid + j * 256, r = i >> 3, c8 = i & 7;
        cp_async16(sB + r * SA + c8 * 8, g_Bbig + (size_t)(n0 + r) * D + ks * 64 + c8 * 8);
    }
    CP_COMMIT();

    float acc[2][4][4];
    #pragma unroll
    for (int a = 0; a < 2; a++)
        #pragma unroll
        for (int b2 = 0; b2 < 4; b2++)
            #pragma unroll
            for (int c = 0; c < 4; c++) acc[a][b2][c] = 0.f;

    CP_WAIT(0); __syncthreads();
    tile_step_small(acc, (uint32_t)__cvta_generic_to_shared(sA),
                    (uint32_t)__cvta_generic_to_shared(sB), aOff0, aOff1, bOff0, bOff1);

    float* cp = g_Ppart + (size_t)ks * NWAY * D;
    #pragma unroll
    for (int mf = 0; mf < 2; mf++) {
        int m = wm * 32 + mf * 16 + g;
        #pragma unroll
        for (int nf = 0; nf < 4; nf++) {
            int c = n0 + wn * 32 + nf * 8 + t4 * 2;
            float2 o0; o0.x = acc[mf][nf][0]; o0.y = acc[mf][nf][1];
            float2 o1; o1.x = acc[mf][nf][2]; o1.y = acc[mf][nf][3];
            *(float2*)(cp + (size_t)m * D + c) = o0;
            *(float2*)(cp + (size_t)(m + 8) * D + c) = o1;
        }
    }
}

// ---------------- pred: P = sum(8 Ppart) + b -> Pbf; pcterm ----------------
__global__ void pred_kernel(const float* __restrict__ bias) {
    int c = blockIdx.x;
    int tid = threadIdx.x;
    float pc = 0.f;
    #pragma unroll
    for (int h = 0; h < 2; h++) {
        int j = tid + h * 256;
        float v = bias[j];
        #pragma unroll
        for (int kp = 0; kp < 8; kp++)
            v += g_Ppart[(size_t)kp * NWAY * D + (size_t)c * D + j];
        g_Pbf[c * D + j] = __float2bfloat16(v);
        pc += v * (v - 2.f * bias[j]);
    }
    #pragma unroll
    for (int o = 16; o > 0; o >>= 1) pc += __shfl_xor_sync(0xffffffffu, pc, o);
    __shared__ float red[8];
    if ((tid & 31) == 0) red[tid >> 5] = pc;
    __syncthreads();
    if (tid == 0) {
        float t2 = 0.f;
        #pragma unroll
        for (int w = 0; w < 8; w++) t2 += red[w];
        g_pcterm[c] = t2;
    }
}

// ---------------- r2: Rpart[js] = Pbf @ W (grid (4 k-tiles, 8 js)) ----------------
__global__ __launch_bounds__(256) void r2_gemm(int dummy) {
    __shared__ __nv_bfloat16 sA[PA];
    __shared__ __nv_bfloat16 sB[PB];
    int tid = threadIdx.x;
    int n0 = blockIdx.x * 128;
    int js = blockIdx.y;
    int warp = tid >> 5, lane = tid & 31;
    int wm = warp & 1, wn = warp >> 1;
    int g = lane >> 2, t4 = lane & 3;

    int aOff0 = (((wm * 32 + 0 + (lane & 15)) * SA + (lane >> 4) * 8)) * 2;
    int aOff1 = (((wm * 32 + 16 + (lane & 15)) * SA + (lane >> 4) * 8)) * 2;
    int bOff0 = (((wn * 32 + 0 + (lane & 7) + ((lane >> 4) << 3)) * SA + ((lane >> 3) & 1) * 8)) * 2;
    int bOff1 = (((wn * 32 + 16 + (lane & 7) + ((lane >> 4) << 3)) * SA + ((lane >> 3) & 1) * 8)) * 2;

    #pragma unroll
    for (int j = 0; j < 2; j++) {
        int i = tid + j * 256, r = i >> 3, c8 = i & 7;
        cp_async16(sA + r * SA + c8 * 8, g_Pbf + (size_t)r * D + js * 64 + c8 * 8);
    }
    #pragma unroll
    for (int j = 0; j < 4; j++) {
        int i = tid + j * 256, r = i >> 3, c8 = i & 7;
        cp_async16(sB + r * SA + c8 * 8, g_WbfT + (size_t)(n0 + r) * D + js * 64 + c8 * 8);
    }
    CP_COMMIT();

    float acc[2][4][4];
    #pragma unroll
    for (int a = 0; a < 2; a++)
        #pragma unroll
        for (int b2 = 0; b2 < 4; b2++)
            #pragma unroll
            for (int c = 0; c < 4; c++) acc[a][b2][c] = 0.f;

    CP_WAIT(0); __syncthreads();
    tile_step_small(acc, (uint32_t)__cvta_generic_to_shared(sA),
                    (uint32_t)__cvta_generic_to_shared(sB), aOff0, aOff1, bOff0, bOff1);

    float* cp = g_Rpart + (size_t)js * NWAY * D;
    #pragma unroll
    for (int mf = 0; mf < 2; mf++) {
        int m = wm * 32 + mf * 16 + g;
        #pragma unroll
        for (int nf = 0; nf < 4; nf++) {
            int c = n0 + wn * 32 + nf * 8 + t4 * 2;
            float2 o0; o0.x = acc[mf][nf][0]; o0.y = acc[mf][nf][1];
            float2 o1; o1.x = acc[mf][nf][2]; o1.y = acc[mf][nf][3];
            *(float2*)(cp + (size_t)m * D + c) = o0;
            *(float2*)(cp + (size_t)(m + 8) * D + c) = o1;
        }
    }
}

// ---------------- rred: R = sum(8 Rpart) -> bf16 ----------------
__global__ void rred_kernel(int dummy) {
    int c = blockIdx.x;
    int k = blockIdx.y * 128 + threadIdx.x;
    float v = 0.f;
    #pragma unroll
    for (int js = 0; js < 8; js++)
        v += g_Rpart[(size_t)js * NWAY * D + (size_t)c * D + k];
    g_Bbig[(size_t)(512 + c) * D + k] = __float2bfloat16(v);
}

// ---------------- main GEMM: CTA 256x128, warp 64x64, 3-stage cp.async ----------------
// grid (M/256, 5): nt 0..3 norm (bias+square), nt 4 cross (Bbig rows 512.., 64 valid)
#define SM_MAIN2 (3 * (ASZ2 + BSZ2) * 2 + 128 * 4)

__global__ __launch_bounds__(256, 1) void main_gemm(const float* __restrict__ bias, int M) {
    extern __shared__ char smc[];
    __nv_bfloat16* sA = (__nv_bfloat16*)smc;
    __nv_bfloat16* sB = (__nv_bfloat16*)smc + 3 * ASZ2;
    float* sbias = (float*)(smc + 3 * (ASZ2 + BSZ2) * 2);

    int tid = threadIdx.x;
    int m0 = blockIdx.x * 256;
    int nt = blockIdx.y;
    int n0 = nt * 128;
    int warp = tid >> 5, lane = tid & 31;
    int wm = warp & 3, wn = warp >> 2;   // 4(M) x 2(N) warps; warp tile 64x64
    int g = lane >> 2, t4 = lane & 3;

    if (nt < 4 && tid < 128) sbias[tid] = bias[n0 + tid];

    int aOffs[4], bOffs[4];
    #pragma unroll
    for (int f = 0; f < 4; f++) {
        aOffs[f] = (((wm * 64 + f * 16 + (lane & 15)) * SA + (lane >> 4) * 8)) * 2;
        bOffs[f] = (((wn * 64 + f * 16 + (lane & 7) + ((lane >> 4) << 3)) * SA
                     + ((lane >> 3) & 1) * 8)) * 2;
    }

    float acc[4][8][4];
    #pragma unroll
    for (int a = 0; a < 4; a++)
        #pragma unroll
        for (int b2 = 0; b2 < 8; b2++)
            #pragma unroll
            for (int c = 0; c < 4; c++) acc[a][b2][c] = 0.f;

    auto loadA = [&](int st, int kt) {
        #pragma unroll
        for (int j = 0; j < 8; j++) {
            int i = tid + j * 256, r = i >> 3, c8 = i & 7;
            int grow = m0 + r; if (grow >= M) grow = M - 1;
            cp_async16(sA + st * ASZ2 + r * SA + c8 * 8,
                       g_qbf + (size_t)grow * D + kt * 64 + c8 * 8);
        }
    };
    auto loadB = [&](int st, int kt) {
        #pragma unroll
        for (int j = 0; j < 4; j++) {
            int i = tid + j * 256, r = i >> 3, c8 = i & 7;
            cp_async16(sB + st * BSZ2 + r * SA + c8 * 8,
                       g_Bbig + (size_t)(n0 + r) * D + kt * 64 + c8 * 8);
        }
    };

    loadA(0, 0); loadB(0, 0); CP_COMMIT();
    loadA(1, 1); loadB(1, 1); CP_COMMIT();

    uint32_t sa0 = (uint32_t)__cvta_generic_to_shared(sA);
    uint32_t sb0 = (uint32_t)__cvta_generic_to_shared(sB);

    #pragma unroll 1
    for (int kt = 0; kt < 8; kt++) {
        if (kt < 7) { CP_WAIT(1); } else { CP_WAIT(0); }
        __syncthreads();
        if (kt + 2 < 8) { loadA((kt + 2) % 3, kt + 2); loadB((kt + 2) % 3, kt + 2); CP_COMMIT(); }

        uint32_t aA = sa0 + ((kt % 3) * ASZ2) * 2;
        uint32_t aB = sb0 + ((kt % 3) * BSZ2) * 2;
        #pragma unroll
        for (int kk = 0; kk < 64; kk += 16) {
            uint32_t br[4][4];
            #pragma unroll
            for (int nf2 = 0; nf2 < 4; nf2++) ldsm4(br[nf2], aB + bOffs[nf2] + kk * 2);
            #pragma unroll
            for (int mf = 0; mf < 4; mf++) {
                uint32_t ar[4];
                ldsm4(ar, aA + aOffs[mf] + kk * 2);
                #pragma unroll
                for (int nf2 = 0; nf2 < 4; nf2++) {
                    mma16816(acc[mf][nf2 * 2],     ar[0], ar[1], ar[2], ar[3], br[nf2][0], br[nf2][1]);
                    mma16816(acc[mf][nf2 * 2 + 1], ar[0], ar[1], ar[2], ar[3], br[nf2][2], br[nf2][3]);
                }
            }
        }
    }

    if (nt < 4) {
        // norm epilogue: each warp covers 64 cols = g_partial group nt*2+wn
        int grp = nt * 2 + wn;
        #pragma unroll
        for (int mf = 0; mf < 4; mf++) {
            float s0 = 0.f, s1 = 0.f;
            #pragma unroll
            for (int nf = 0; nf < 8; nf++) {
                int c = wn * 64 + nf * 8 + t4 * 2;
                float b0 = sbias[c], b1 = sbias[c + 1];
                float v;
                v = acc[mf][nf][0] + b0; s0 += v * v;
                v = acc[mf][nf][1] + b1; s0 += v * v;
                v = acc[mf][nf][2] + b0; s1 += v * v;
                v = acc[mf][nf][3] + b1; s1 += v * v;
            }
            s0 += __shfl_xor_sync(0xffffffffu, s0, 1);
            s0 += __shfl_xor_sync(0xffffffffu, s0, 2);
            s1 += __shfl_xor_sync(0xffffffffu, s1, 1);
            s1 += __shfl_xor_sync(0xffffffffu, s1, 2);
            if (t4 == 0) {
                int r = wm * 64 + mf * 16 + g;
                if (m0 + r < M)     g_partial[(size_t)(m0 + r) * 8 + grp] = s0;
                if (m0 + r + 8 < M) g_partial[(size_t)(m0 + r + 8) * 8 + grp] = s1;
            }
        }
    } else if (wn == 0) {
        // cross epilogue: cols 0..63 valid (classes)
        #pragma unroll
        for (int mf = 0; mf < 4; mf++) {
            int r = wm * 64 + mf * 16 + g;
            #pragma unroll
            for (int nf = 0; nf < 8; nf++) {
                int c = nf * 8 + t4 * 2;
                if (m0 + r < M) {
                    float2 o; o.x = acc[mf][nf][0]; o.y = acc[mf][nf][1];
                    *(float2*)(g_cross + (size_t)(m0 + r) * NWAY + c) = o;
                }
                if (m0 + r + 8 < M) {
                    float2 o; o.x = acc[mf][nf][2]; o.y = acc[mf][nf][3];
                    *(float2*)(g_cross + (size_t)(m0 + r + 8) * NWAY + c) = o;
                }
            }
        }
    }
}

// ---------------- combine: dist = nq + pcterm - 2*cross ----------------
__global__ void combine_kernel(float* __restrict__ out, int M) {
    __shared__ float snq[4];
    int tid = threadIdx.x;
    int q0 = blockIdx.x * 4;
    if (tid < 4 && q0 + tid < M) {
        float s = 0.f;
        #pragma unroll
        for (int t = 0; t < 8; t++) s += g_partial[(size_t)(q0 + tid) * 8 + t];
        snq[tid] = s;
    }
    __syncthreads();
    int q = q0 + (tid >> 6), c = tid & 63;
    if (q < M)
        out[(size_t)q * NWAY + c] = snq[tid >> 6] + g_pcterm[c]
                                    - 2.f * g_cross[(size_t)q * NWAY + c];
}

// ---------------- launch (single stream) ----------------
extern "C" void kernel_launch(void* const* d_in, const int* in_sizes, int n_in,
                              void* d_out, int out_size) {
    const float* support = (const float*)d_in[0];
    const float* query   = (const float*)d_in[1];
    const float* W       = (const float*)d_in[2];
    const float* bias    = (const float*)d_in[3];
    int M = in_sizes[1] / D;
    if (M > MAXQ) M = MAXQ;
    float* out = (float*)d_out;
    int qblocks = (int)(((size_t)M * D + 2047) / 2048);
    int mblocks = (M + 255) / 256;

    cudaFuncSetAttribute(main_gemm, cudaFuncAttributeMaxDynamicSharedMemorySize, SM_MAIN2);

    prep_q_kernel<<<qblocks, 256>>>(query, M);
    prep_w_kernel<<<256 + 64 + 64 + 16, 256>>>(W, support);
    proj_gemm<<<dim3(4, 8), 256>>>(0);
    pred_kernel<<<NWAY, 256>>>(bias);
    r2_gemm<<<dim3(4, 8), 256>>>(0);
    rred_kernel<<<dim3(NWAY, 4), 128>>>(0);
    main_gemm<<<dim3(mblocks, 5), 256, SM_MAIN2>>>(bias, M);
    combine_kernel<<<(M + 3) / 4, 256>>>(out, M);
}

// round 15
// speedup vs baseline: 1.1789x; 1.1789x over previous
#include <cuda_runtime.h>
#include <cuda_bf16.h>
#include <cstdint>

#define D      512
#define NWAY   64
#define KSHOT  16
#define MAXQ   8192
#define SA     72            // smem K-stride (bf16): 144B rows, LDSM conflict-free
#define PA     (64 * SA)
#define PB     (128 * SA)
#define ASZ3   (128 * SA)    // main A stage elems (128 rows)
#define BSZ3   (128 * SA)    // main B stage elems (128 rows)

// ---------------- device scratch ----------------
__device__ __nv_bfloat16  g_smeanbf[NWAY * D];
__device__ __nv_bfloat16  g_Pbf[NWAY * D];
__device__ float          g_Ppart[8 * NWAY * D];
__device__ float          g_Rpart[8 * NWAY * D];
__device__ float          g_pcpart[4 * NWAY];
__device__ __nv_bfloat16  g_qbf[(size_t)MAXQ * D];
__device__ __nv_bfloat16  g_Bbig[(512 + 128) * D];   // 0..511 W, 512..575 R, 576..639 zero pad
__device__ __nv_bfloat16  g_WbfT[D * D];
__device__ float          g_partial[(size_t)MAXQ * 8];
__device__ float          g_cross[(size_t)MAXQ * NWAY];

// ---------------- mma / ldmatrix / cp.async helpers ----------------
__device__ __forceinline__ void mma16816(float* c,
                                         uint32_t a0, uint32_t a1, uint32_t a2, uint32_t a3,
                                         uint32_t b0, uint32_t b1) {
    asm volatile(
        "mma.sync.aligned.m16n8k16.row.col.f32.bf16.bf16.f32 "
        "{%0,%1,%2,%3},{%4,%5,%6,%7},{%8,%9},{%0,%1,%2,%3};\n"
        : "+f"(c[0]), "+f"(c[1]), "+f"(c[2]), "+f"(c[3])
        : "r"(a0), "r"(a1), "r"(a2), "r"(a3), "r"(b0), "r"(b1));
}
__device__ __forceinline__ void ldsm4(uint32_t* r, uint32_t a) {
    asm volatile("ldmatrix.sync.aligned.m8n8.x4.shared.b16 {%0,%1,%2,%3}, [%4];"
                 : "=r"(r[0]), "=r"(r[1]), "=r"(r[2]), "=r"(r[3]) : "r"(a));
}
__device__ __forceinline__ void cp_async16(void* smem, const void* gmem) {
    uint32_t s = (uint32_t)__cvta_generic_to_shared(smem);
    asm volatile("cp.async.cg.shared.global [%0], [%1], 16;\n" :: "r"(s), "l"(gmem));
}
#define CP_COMMIT() asm volatile("cp.async.commit_group;\n")
#define CP_WAIT(n)  asm volatile("cp.async.wait_group %0;\n" :: "n"(n))

// Small-tile step (64Mx128N CTA, warp 32x32): prologue GEMMs
__device__ __forceinline__ void tile_step_small(float acc[2][4][4], uint32_t aA, uint32_t aB,
                                                int aOff0, int aOff1, int bOff0, int bOff1) {
    #pragma unroll
    for (int kk = 0; kk < 64; kk += 16) {
        uint32_t br0[4], br1[4];
        ldsm4(br0, aB + bOff0 + kk * 2);
        ldsm4(br1, aB + bOff1 + kk * 2);
        #pragma unroll
        for (int mf = 0; mf < 2; mf++) {
            uint32_t ar[4];
            ldsm4(ar, aA + (mf ? aOff1 : aOff0) + kk * 2);
            mma16816(acc[mf][0], ar[0], ar[1], ar[2], ar[3], br0[0], br0[1]);
            mma16816(acc[mf][1], ar[0], ar[1], ar[2], ar[3], br0[2], br0[3]);
            mma16816(acc[mf][2], ar[0], ar[1], ar[2], ar[3], br1[0], br1[1]);
            mma16816(acc[mf][3], ar[0], ar[1], ar[2], ar[3], br1[2], br1[3]);
        }
    }
}

// ---------------- prep_q: Q -> bf16 ----------------
__global__ void prep_q_kernel(const float* __restrict__ q, int M) {
    size_t total = (size_t)M * D;
    size_t base = (size_t)blockIdx.x * 2048 + threadIdx.x * 8;
    if (base + 8 <= total) {
        float4 v0 = *(const float4*)(q + base);
        float4 v1 = *(const float4*)(q + base + 4);
        __nv_bfloat162 p0 = __floats2bfloat162_rn(v0.x, v0.y);
        __nv_bfloat162 p1 = __floats2bfloat162_rn(v0.z, v0.w);
        __nv_bfloat162 p2 = __floats2bfloat162_rn(v1.x, v1.y);
        __nv_bfloat162 p3 = __floats2bfloat162_rn(v1.z, v1.w);
        uint4 o;
        o.x = *(uint32_t*)&p0; o.y = *(uint32_t*)&p1;
        o.z = *(uint32_t*)&p2; o.w = *(uint32_t*)&p3;
        *(uint4*)(g_qbf + base) = o;
    } else {
        for (int e = 0; e < 8; e++)
            if (base + e < total) g_qbf[base + e] = __float2bfloat16(q[base + e]);
    }
}

// ---------------- prep_w: W->bf16, W^T, smean, zero pad ----------------
__global__ void prep_w_kernel(const float* __restrict__ W,
                              const float* __restrict__ support) {
    int b = blockIdx.x;
    int tid = threadIdx.x;
    if (b < 256) {
        int base = b * 1024 + tid * 4;
        float4 v = *(const float4*)(W + base);
        *(__nv_bfloat162*)(g_Bbig + base)     = __floats2bfloat162_rn(v.x, v.y);
        *(__nv_bfloat162*)(g_Bbig + base + 2) = __floats2bfloat162_rn(v.z, v.w);
    } else if (b < 256 + 64) {
        __shared__ float ts[64][68];
        int t = b - 256;
        int r0 = (t >> 3) * 64, c0 = (t & 7) * 64;
        #pragma unroll
        for (int it = 0; it < 4; it++) {
            int r = (tid >> 4) + it * 16;
            float4 v = *(const float4*)(W + (size_t)(r0 + r) * D + c0 + (tid & 15) * 4);
            ts[r][(tid & 15) * 4 + 0] = v.x; ts[r][(tid & 15) * 4 + 1] = v.y;
            ts[r][(tid & 15) * 4 + 2] = v.z; ts[r][(tid & 15) * 4 + 3] = v.w;
        }
        __syncthreads();
        int kk = tid >> 2, jb = (tid & 3) * 16;
        #pragma unroll
        for (int e = 0; e < 16; e += 2) {
            *(__nv_bfloat162*)(g_WbfT + (size_t)(c0 + kk) * D + r0 + jb + e) =
                __floats2bfloat162_rn(ts[jb + e][kk], ts[jb + e + 1][kk]);
        }
    } else if (b < 256 + 64 + 64) {
        int c = b - 256 - 64;
        for (int col = tid; col < D; col += blockDim.x) {
            float s = 0.f;
            #pragma unroll
            for (int k = 0; k < KSHOT; k++) s += support[(size_t)(c * KSHOT + k) * D + col];
            g_smeanbf[c * D + col] = __float2bfloat16(s * (1.f / KSHOT));
        }
    } else {
        // zero pad rows 576..639 of Bbig
        int t = b - 256 - 64 - 64;
        uint4 z = make_uint4(0u, 0u, 0u, 0u);
        *(uint4*)(g_Bbig + (size_t)576 * D + (size_t)t * 2048 + tid * 8) = z;
    }
}

// ---------------- proj: Ppart[ks] = smeanbf @ W^T (grid (4 j-tiles, 8 ks)) ----------------
__global__ __launch_bounds__(256) void proj_gemm(int dummy) {
    __shared__ __nv_bfloat16 sA[PA];
    __shared__ __nv_bfloat16 sB[PB];
    int tid = threadIdx.x;
    int n0 = blockIdx.x * 128;
    int ks = blockIdx.y;
    int warp = tid >> 5, lane = tid & 31;
    int wm = warp & 1, wn = warp >> 1;
    int g = lane >> 2, t4 = lane & 3;

    int aOff0 = (((wm * 32 + 0 + (lane & 15)) * SA + (lane >> 4) * 8)) * 2;
    int aOff1 = (((wm * 32 + 16 + (lane & 15)) * SA + (lane >> 4) * 8)) * 2;
    int bOff0 = (((wn * 32 + 0 + (lane & 7) + ((lane >> 4) << 3)) * SA + ((lane >> 3) & 1) * 8)) * 2;
    int bOff1 = (((wn * 32 + 16 + (lane & 7) + ((lane >> 4) << 3)) * SA + ((lane >> 3) & 1) * 8)) * 2;

    #pragma unroll
    for (int j = 0; j < 2; j++) {
        int i = tid + j * 256, r = i >> 3, c8 = i & 7;
        cp_async16(sA + r * SA + c8 * 8, g_smeanbf + (size_t)r * D + ks * 64 + c8 * 8);
    }
    #pragma unroll
    for (int j = 0; j < 4; j++) {
        int i = tid + j * 256, r = i >> 3, c8 = i & 7;
        cp_async16(sB + r * SA + c8 * 8, g_Bbig + (size_t)(n0 + r) * D + ks * 64 + c8 * 8);
    }
    CP_COMMIT();

    float acc[2][4][4];
    #pragma unroll
    for (int a = 0; a < 2; a++)
        #pragma unroll
        for (int b2 = 0; b2 < 4; b2++)
            #pragma unroll
            for (int c = 0; c < 4; c++) acc[a][b2][c] = 0.f;

    CP_WAIT(0); __syncthreads();
    tile_step_small(acc, (uint32_t)__cvta_generic_to_shared(sA),
                    (uint32_t)__cvta_generic_to_shared(sB), aOff0, aOff1, bOff0, bOff1);

    float* cp = g_Ppart + (size_t)ks * NWAY * D;
    #pragma unroll
    for (int mf = 0; mf < 2; mf++) {
        int m = wm * 32 + mf * 16 + g;
        #pragma unroll
        for (int nf = 0; nf < 4; nf++) {
            int c = n0 + wn * 32 + nf * 8 + t4 * 2;
            float2 o0; o0.x = acc[mf][nf][0]; o0.y = acc[mf][nf][1];
            float2 o1; o1.x = acc[mf][nf][2]; o1.y = acc[mf][nf][3];
            *(float2*)(cp + (size_t)m * D + c) = o0;
            *(float2*)(cp + (size_t)(m + 8) * D + c) = o1;
        }
    }
}

// ---------------- pred: grid (64 classes, 4 j-chunks): P -> Pbf; pcterm partials ----------------
__global__ void pred_kernel(const float* __restrict__ bias) {
    int c = blockIdx.x;
    int jq = blockIdx.y;
    int tid = threadIdx.x;           // 128
    int j = jq * 128 + tid;
    float b = bias[j];
    float v = b;
    #pragma unroll
    for (int kp = 0; kp < 8; kp++)
        v += g_Ppart[(size_t)kp * NWAY * D + (size_t)c * D + j];
    g_Pbf[c * D + j] = __float2bfloat16(v);
    float pc = v * (v - 2.f * b);
    #pragma unroll
    for (int o = 16; o > 0; o >>= 1) pc += __shfl_xor_sync(0xffffffffu, pc, o);
    __shared__ float red[4];
    if ((tid & 31) == 0) red[tid >> 5] = pc;
    __syncthreads();
    if (tid == 0) g_pcpart[jq * NWAY + c] = red[0] + red[1] + red[2] + red[3];
}

// ---------------- r2: Rpart[js] = Pbf @ W (grid (4 k-tiles, 8 js)) ----------------
__global__ __launch_bounds__(256) void r2_gemm(int dummy) {
    __shared__ __nv_bfloat16 sA[PA];
    __shared__ __nv_bfloat16 sB[PB];
    int tid = threadIdx.x;
    int n0 = blockIdx.x * 128;
    int js = blockIdx.y;
    int warp = tid >> 5, lane = tid & 31;
    int wm = warp & 1, wn = warp >> 1;
    int g = lane >> 2, t4 = lane & 3;

    int aOff0 = (((wm * 32 + 0 + (lane & 15)) * SA + (lane >> 4) * 8)) * 2;
    int aOff1 = (((wm * 32 + 16 + (lane & 15)) * SA + (lane >> 4) * 8)) * 2;
    int bOff0 = (((wn * 32 + 0 + (lane & 7) + ((lane >> 4) << 3)) * SA + ((lane >> 3) & 1) * 8)) * 2;
    int bOff1 = (((wn * 32 + 16 + (lane & 7) + ((lane >> 4) << 3)) * SA + ((lane >> 3) & 1) * 8)) * 2;

    #pragma unroll
    for (int j = 0; j < 2; j++) {
        int i = tid + j * 256, r = i >> 3, c8 = i & 7;
        cp_async16(sA + r * SA + c8 * 8, g_Pbf + (size_t)r * D + js * 64 + c8 * 8);
    }
    #pragma unroll
    for (int j = 0; j < 4; j++) {
        int i = tid + j * 256, r = i >> 3, c8 = i & 7;
        cp_async16(sB + r * SA + c8 * 8, g_WbfT + (size_t)(n0 + r) * D + js * 64 + c8 * 8);
    }
    CP_COMMIT();

    float acc[2][4][4];
    #pragma unroll
    for (int a = 0; a < 2; a++)
        #pragma unroll
        for (int b2 = 0; b2 < 4; b2++)
            #pragma unroll
            for (int c = 0; c < 4; c++) acc[a][b2][c] = 0.f;

    CP_WAIT(0); __syncthreads();
    tile_step_small(acc, (uint32_t)__cvta_generic_to_shared(sA),
                    (uint32_t)__cvta_generic_to_shared(sB), aOff0, aOff1, bOff0, bOff1);

    float* cp = g_Rpart + (size_t)js * NWAY * D;
    #pragma unroll
    for (int mf = 0; mf < 2; mf++) {
        int m = wm * 32 + mf * 16 + g;
        #pragma unroll
        for (int nf = 0; nf < 4; nf++) {
            int c = n0 + wn * 32 + nf * 8 + t4 * 2;
            float2 o0; o0.x = acc[mf][nf][0]; o0.y = acc[mf][nf][1];
            float2 o1; o1.x = acc[mf][nf][2]; o1.y = acc[mf][nf][3];
            *(float2*)(cp + (size_t)m * D + c) = o0;
            *(float2*)(cp + (size_t)(m + 8) * D + c) = o1;
        }
    }
}

// ---------------- rred: R = sum(8 Rpart) -> bf16 ----------------
__global__ void rred_kernel(int dummy) {
    int c = blockIdx.x;
    int k = blockIdx.y * 128 + threadIdx.x;
    float v = 0.f;
    #pragma unroll
    for (int js = 0; js < 8; js++)
        v += g_Rpart[(size_t)js * NWAY * D + (size_t)c * D + k];
    g_Bbig[(size_t)(512 + c) * D + k] = __float2bfloat16(v);
}

// ---------------- main GEMM: CTA 128x128, warp 32x64, 3-stage, 2 CTA/SM ----------------
// grid (M/128, 5): nt 0..3 norm (bias+square), nt 4 cross (Bbig rows 512..639)
#define SM_MAIN3 (3 * (ASZ3 + BSZ3) * 2 + 128 * 4)

__global__ __launch_bounds__(256, 2) void main_gemm(const float* __restrict__ bias, int M) {
    extern __shared__ char smc[];
    __nv_bfloat16* sA = (__nv_bfloat16*)smc;
    __nv_bfloat16* sB = (__nv_bfloat16*)smc + 3 * ASZ3;
    float* sbias = (float*)(smc + 3 * (ASZ3 + BSZ3) * 2);

    int tid = threadIdx.x;
    int m0 = blockIdx.x * 128;
    int nt = blockIdx.y;
    int n0 = nt * 128;
    int warp = tid >> 5, lane = tid & 31;
    int wm = warp & 3, wn = warp >> 2;   // 4(M) x 2(N) warps; warp tile 32x64
    int g = lane >> 2, t4 = lane & 3;

    if (nt < 4 && tid < 128) sbias[tid] = bias[n0 + tid];

    int aOffs[2], bOffs[4];
    #pragma unroll
    for (int f = 0; f < 2; f++)
        aOffs[f] = (((wm * 32 + f * 16 + (lane & 15)) * SA + (lane >> 4) * 8)) * 2;
    #pragma unroll
    for (int f = 0; f < 4; f++)
        bOffs[f] = (((wn * 64 + f * 16 + (lane & 7) + ((lane >> 4) << 3)) * SA
                     + ((lane >> 3) & 1) * 8)) * 2;

    float acc[2][8][4];
    #pragma unroll
    for (int a = 0; a < 2; a++)
        #pragma unroll
        for (int b2 = 0; b2 < 8; b2++)
            #pragma unroll
            for (int c = 0; c < 4; c++) acc[a][b2][c] = 0.f;

    auto loadA = [&](int st, int kt) {
        #pragma unroll
        for (int j = 0; j < 4; j++) {
            int i = tid + j * 256, r = i >> 3, c8 = i & 7;
            int grow = m0 + r; if (grow >= M) grow = M - 1;
            cp_async16(sA + st * ASZ3 + r * SA + c8 * 8,
                       g_qbf + (size_t)grow * D + kt * 64 + c8 * 8);
        }
    };
    auto loadB = [&](int st, int kt) {
        #pragma unroll
        for (int j = 0; j < 4; j++) {
            int i = tid + j * 256, r = i >> 3, c8 = i & 7;
            cp_async16(sB + st * BSZ3 + r * SA + c8 * 8,
                       g_Bbig + (size_t)(n0 + r) * D + kt * 64 + c8 * 8);
        }
    };

    loadA(0, 0); loadB(0, 0); CP_COMMIT();
    loadA(1, 1); loadB(1, 1); CP_COMMIT();

    uint32_t sa0 = (uint32_t)__cvta_generic_to_shared(sA);
    uint32_t sb0 = (uint32_t)__cvta_generic_to_shared(sB);

    #pragma unroll 1
    for (int kt = 0; kt < 8; kt++) {
        if (kt < 7) { CP_WAIT(1); } else { CP_WAIT(0); }
        __syncthreads();
        if (kt + 2 < 8) { loadA((kt + 2) % 3, kt + 2); loadB((kt + 2) % 3, kt + 2); CP_COMMIT(); }

        uint32_t aA = sa0 + ((kt % 3) * ASZ3) * 2;
        uint32_t aB = sb0 + ((kt % 3) * BSZ3) * 2;
        #pragma unroll
        for (int kk = 0; kk < 64; kk += 16) {
            uint32_t br[4][4];
            #pragma unroll
            for (int nf2 = 0; nf2 < 4; nf2++) ldsm4(br[nf2], aB + bOffs[nf2] + kk * 2);
            #pragma unroll
            for (int mf = 0; mf < 2; mf++) {
                uint32_t ar[4];
                ldsm4(ar, aA + aOffs[mf] + kk * 2);
                #pragma unroll
                for (int nf2 = 0; nf2 < 4; nf2++) {
                    mma16816(acc[mf][nf2 * 2],     ar[0], ar[1], ar[2], ar[3], br[nf2][0], br[nf2][1]);
                    mma16816(acc[mf][nf2 * 2 + 1], ar[0], ar[1], ar[2], ar[3], br[nf2][2], br[nf2][3]);
                }
            }
        }
    }

    if (nt < 4) {
        // norm epilogue: warp covers 64 cols -> g_partial group nt*2+wn
        int grp = nt * 2 + wn;
        #pragma unroll
        for (int mf = 0; mf < 2; mf++) {
            float s0 = 0.f, s1 = 0.f;
            #pragma unroll
            for (int nf = 0; nf < 8; nf++) {
                int c = wn * 64 + nf * 8 + t4 * 2;
                float b0 = sbias[c], b1 = sbias[c + 1];
                float v;
                v = acc[mf][nf][0] + b0; s0 += v * v;
                v = acc[mf][nf][1] + b1; s0 += v * v;
                v = acc[mf][nf][2] + b0; s1 += v * v;
                v = acc[mf][nf][3] + b1; s1 += v * v;
            }
            s0 += __shfl_xor_sync(0xffffffffu, s0, 1);
            s0 += __shfl_xor_sync(0xffffffffu, s0, 2);
            s1 += __shfl_xor_sync(0xffffffffu, s1, 1);
            s1 += __shfl_xor_sync(0xffffffffu, s1, 2);
            if (t4 == 0) {
                int r = wm * 32 + mf * 16 + g;
                if (m0 + r < M)     g_partial[(size_t)(m0 + r) * 8 + grp] = s0;
                if (m0 + r + 8 < M) g_partial[(size_t)(m0 + r + 8) * 8 + grp] = s1;
            }
        }
    } else if (wn == 0) {
        // cross epilogue: cols 0..63 valid (classes)
        #pragma unroll
        for (int mf = 0; mf < 2; mf++) {
            int r = wm * 32 + mf * 16 + g;
            #pragma unroll
            for (int nf = 0; nf < 8; nf++) {
                int c = nf * 8 + t4 * 2;
                if (m0 + r < M) {
                    float2 o; o.x = acc[mf][nf][0]; o.y = acc[mf][nf][1];
                    *(float2*)(g_cross + (size_t)(m0 + r) * NWAY + c) = o;
                }
                if (m0 + r + 8 < M) {
                    float2 o; o.x = acc[mf][nf][2]; o.y = acc[mf][nf][3];
                    *(float2*)(g_cross + (size_t)(m0 + r + 8) * NWAY + c) = o;
                }
            }
        }
    }
}

// ---------------- combine: dist = nq + pcterm - 2*cross ----------------
__global__ void combine_kernel(float* __restrict__ out, int M) {
    __shared__ float snq[4];
    int tid = threadIdx.x;
    int q0 = blockIdx.x * 4;
    if (tid < 4 && q0 + tid < M) {
        float s = 0.f;
        #pragma unroll
        for (int t = 0; t < 8; t++) s += g_partial[(size_t)(q0 + tid) * 8 + t];
        snq[tid] = s;
    }
    __syncthreads();
    int q = q0 + (tid >> 6), c = tid & 63;
    if (q < M) {
        float pc = g_pcpart[c] + g_pcpart[NWAY + c]
                 + g_pcpart[2 * NWAY + c] + g_pcpart[3 * NWAY + c];
        out[(size_t)q * NWAY + c] = snq[tid >> 6] + pc
                                    - 2.f * g_cross[(size_t)q * NWAY + c];
    }
}

// ---------------- launch (single stream) ----------------
extern "C" void kernel_launch(void* const* d_in, const int* in_sizes, int n_in,
                              void* d_out, int out_size) {
    const float* support = (const float*)d_in[0];
    const float* query   = (const float*)d_in[1];
    const float* W       = (const float*)d_in[2];
    const float* bias    = (const float*)d_in[3];
    int M = in_sizes[1] / D;
    if (M > MAXQ) M = MAXQ;
    float* out = (float*)d_out;
    int qblocks = (int)(((size_t)M * D + 2047) / 2048);
    int mblocks = (M + 127) / 128;

    cudaFuncSetAttribute(main_gemm, cudaFuncAttributeMaxDynamicSharedMemorySize, SM_MAIN3);

    prep_q_kernel<<<qblocks, 256>>>(query, M);
    prep_w_kernel<<<256 + 64 + 64 + 16, 256>>>(W, support);
    proj_gemm<<<dim3(4, 8), 256>>>(0);
    pred_kernel<<<dim3(NWAY, 4), 128>>>(bias);
    r2_gemm<<<dim3(4, 8), 256>>>(0);
    rred_kernel<<<dim3(NWAY, 4), 128>>>(0);
    main_gemm<<<dim3(mblocks, 5), 256, SM_MAIN3>>>(bias, M);
    combine_kernel<<<(M + 3) / 4, 256>>>(out, M);
}